// round 3
// baseline (speedup 1.0000x reference)
#include <cuda_runtime.h>
#include <cuda_bf16.h>
#include <math.h>

// Problem constants (GCNAggregator): B=4096, K=32, U=32768, V=100000, D=128
#define GCN_B 4096
#define GCN_K 32
#define GCN_U 32768
#define GCN_D 128

#define NB 512                 // grid size (must be <= co-resident capacity)
#define NT 256                 // threads per block (8 warps = 8 rows per block)
#define ROWS_PER_BLOCK 8

// Persistent device scratch. INVARIANT: all of this is 0 at every kernel entry
// (zero-initialized at module load; restored to 0 by the kernel itself before exit).
__device__ int g_col_deg[GCN_U];
__device__ int g_cntB;
__device__ int g_cntC;
__device__ volatile int g_flagB;
__device__ volatile int g_flagC;

__global__ void __launch_bounds__(NT, 4)
gcn_fused_kernel(const int* __restrict__ neigh_cols,
                 const int* __restrict__ unique_ids,
                 const float4* __restrict__ embed_table4,  // [V, 32] float4
                 float4* __restrict__ out4) {              // [B, 32] float4
    const int tid  = threadIdx.x;
    const int blk  = blockIdx.x;
    const int warp = tid >> 5;
    const int lane = tid & 31;
    const int b    = blk * ROWS_PER_BLOCK + warp;

    __shared__ int2 s_wo[ROWS_PER_BLOCK][GCN_K];  // {row offset in float4 units, bitcast(weight)}

    // ---------------- Phase 1: per-warp dedupe + degree histogram ----------------
    const int c = neigh_cols[b * GCN_K + lane];
    bool first = true;
    #pragma unroll
    for (int j = 0; j < GCN_K; j++) {
        int cj = __shfl_sync(0xFFFFFFFFu, c, j);
        if (j < lane && cj == c) first = false;
    }
    const unsigned mask = __ballot_sync(0xFFFFFFFFu, first);
    if (first) atomicAdd(&g_col_deg[c], 1);

    // ---------------- Barrier B: all degree atomics complete ----------------
    __syncthreads();
    if (tid == 0) {
        __threadfence();
        int t = atomicAdd(&g_cntB, 1);
        if (t == NB - 1) { __threadfence(); g_flagB = 1; }
        while (g_flagB == 0) __nanosleep(20);
        __threadfence();
    }
    __syncthreads();

    // ---------------- Phase 2: read degrees -> weights, stage into smem ----------------
    // __ldcg: read at L2 scope (atomics landed in L2; this SM never L1-cached col_deg).
    float w = 0.0f;
    if (first) {
        int deg = __ldcg(&g_col_deg[c]);     // deg >= 1 here, so 1/max(sqrt(deg),1) == rsqrt(deg)
        w = rsqrtf((float)deg);
    }
    const int off4 = unique_ids[c] * (GCN_D / 4);
    // STS data-depends on the degree load; BAR.SYNC below drains pending STS,
    // so barrier C orders ALL degree reads before any block re-zeroes col_deg.
    s_wo[warp][lane] = make_int2(off4, __float_as_int(w));

    // ---------------- Barrier C: all degree reads complete ----------------
    __syncthreads();
    if (tid == 0) {
        int t = atomicAdd(&g_cntC, 1);
        if (t == NB - 1) {
            // Everyone passed barrier B -> safe to reset its state for the next replay.
            g_cntB = 0; g_flagB = 0;
            __threadfence();
            g_flagC = 1;
        }
        while (g_flagC == 0) __nanosleep(20);
        __threadfence();
    }
    __syncthreads();

    // ---------------- Phase 3a: restore col_deg = 0 (invariant for next replay) ----------------
    const int gid = blk * NT + tid;
    if (gid < GCN_U) g_col_deg[gid] = 0;

    // ---------------- Phase 3b: aggregate (one warp per row, float4 per lane) ----------------
    float4 acc = make_float4(0.f, 0.f, 0.f, 0.f);
    #pragma unroll
    for (int k = 0; k < GCN_K; k++) {
        int2 wo = s_wo[warp][k];
        float wk = __int_as_float(wo.y);
        float4 v = __ldg(&embed_table4[wo.x + lane]);
        acc.x = fmaf(wk, v.x, acc.x);
        acc.y = fmaf(wk, v.y, acc.y);
        acc.z = fmaf(wk, v.z, acc.z);
        acc.w = fmaf(wk, v.w, acc.w);
    }

    const float rs = rsqrtf((float)__popc(mask));
    acc.x *= rs; acc.y *= rs; acc.z *= rs; acc.w *= rs;
    out4[b * (GCN_D / 4) + lane] = acc;

    // ---------------- Epilogue: self-reset barrier C state ----------------
    // Each block decrements only after it passed C, so flagC stays 1 until the
    // last block (old value 1) resets it. cntC returns to 0 naturally.
    if (tid == 0) {
        int t = atomicSub(&g_cntC, 1);
        if (t == 1) g_flagC = 0;
    }
}

// ---------------------------------------------------------------------------
extern "C" void kernel_launch(void* const* d_in, const int* in_sizes, int n_in,
                              void* d_out, int out_size) {
    const int*    neigh_cols   = (const int*)d_in[0];
    const int*    unique_ids   = (const int*)d_in[1];
    const float4* embed_table4 = (const float4*)d_in[2];
    float4*       out4         = (float4*)d_out;

    gcn_fused_kernel<<<NB, NT>>>(neigh_cols, unique_ids, embed_table4, out4);
}

// round 4
// speedup vs baseline: 1.5489x; 1.5489x over previous
#include <cuda_runtime.h>
#include <cuda_bf16.h>
#include <math.h>

// Problem constants (GCNAggregator): B=4096, K=32, U=32768, V=100000, D=128
#define GCN_B 4096
#define GCN_K 32
#define GCN_U 32768
#define GCN_D 128
#define AGG_WARPS 4      // rows (warps) per aggregate block

// Scratch (no cudaMalloc allowed)
__device__ int      g_col_deg[GCN_U];
__device__ unsigned g_row_mask[GCN_B];  // bit k set = k-th entry is first occurrence in its row

// ---------------------------------------------------------------------------
// Kernel 1: zero column degrees (vectorized: one STG.128 per thread)
// 32768 ints = 8192 int4 -> 32 blocks x 256 threads
// ---------------------------------------------------------------------------
__global__ void zero_col_deg_kernel() {
    int i = blockIdx.x * blockDim.x + threadIdx.x;
    reinterpret_cast<int4*>(g_col_deg)[i] = make_int4(0, 0, 0, 0);
}

// ---------------------------------------------------------------------------
// Kernel 2: per-row dedupe (one warp per row) + column degree accumulation
// ---------------------------------------------------------------------------
__global__ void dedupe_degree_kernel(const int* __restrict__ neigh_cols) {
    int warp_in_block = threadIdx.x >> 5;
    int lane = threadIdx.x & 31;
    int b = blockIdx.x * (blockDim.x >> 5) + warp_in_block;

    int c = neigh_cols[b * GCN_K + lane];

    // first occurrence: no lane j < lane holds the same column
    bool first = true;
    #pragma unroll
    for (int j = 0; j < GCN_K; j++) {
        int cj = __shfl_sync(0xFFFFFFFFu, c, j);
        if (j < lane && cj == c) first = false;
    }

    unsigned mask = __ballot_sync(0xFFFFFFFFu, first);
    if (lane == 0) g_row_mask[b] = mask;
    if (first) atomicAdd(&g_col_deg[c], 1);   // spread addresses -> cheap
}

// ---------------------------------------------------------------------------
// Kernel 3: aggregation. One WARP per row, lane owns 4 consecutive dims.
// Explicit depth-8 software pipeline of LDG.128 gathers; (off, w) broadcast
// from lane registers via shfl (no smem, no block sync). Row scale folded
// into per-lane weights. Duplicates carry w=0 -> branch-free.
// ---------------------------------------------------------------------------
__global__ void __launch_bounds__(32 * AGG_WARPS)
aggregate_kernel(const int* __restrict__ neigh_cols,
                 const int* __restrict__ unique_ids,
                 const float4* __restrict__ embed_table4,  // [V, 32] float4
                 float4* __restrict__ out4) {              // [B, 32] float4
    const int warp = threadIdx.x >> 5;
    const int lane = threadIdx.x & 31;
    const int b = blockIdx.x * AGG_WARPS + warp;

    // ---- prologue: per-lane (offset, weight) ----
    const unsigned mask = g_row_mask[b];
    const int c = neigh_cols[b * GCN_K + lane];
    const bool first = (mask >> lane) & 1u;

    float w = 0.0f;
    if (first) {
        int deg = __ldg(&g_col_deg[c]);       // deg >= 1 for first occurrences
        w = rsqrtf((float)deg);
    }
    w *= rsqrtf((float)__popc(mask));         // fold row scale into lane weight
    const int off4 = __ldg(&unique_ids[c]) * (GCN_D / 4);

    // ---- depth-8 software-pipelined gather ----
    constexpr int P = 8;
    float4 buf[P];
    float  wbuf[P];
    #pragma unroll
    for (int k = 0; k < P; k++) {
        int o = __shfl_sync(0xFFFFFFFFu, off4, k);
        wbuf[k] = __shfl_sync(0xFFFFFFFFu, w, k);
        buf[k] = __ldg(&embed_table4[o + lane]);
    }

    float4 acc = make_float4(0.f, 0.f, 0.f, 0.f);
    #pragma unroll
    for (int k = 0; k < GCN_K; k++) {
        float4 v = buf[k & (P - 1)];
        float wk = wbuf[k & (P - 1)];
        acc.x = fmaf(wk, v.x, acc.x);
        acc.y = fmaf(wk, v.y, acc.y);
        acc.z = fmaf(wk, v.z, acc.z);
        acc.w = fmaf(wk, v.w, acc.w);
        if (k + P < GCN_K) {
            int o = __shfl_sync(0xFFFFFFFFu, off4, k + P);
            wbuf[k & (P - 1)] = __shfl_sync(0xFFFFFFFFu, w, k + P);
            buf[k & (P - 1)] = __ldg(&embed_table4[o + lane]);
        }
    }

    out4[b * (GCN_D / 4) + lane] = acc;
}

// ---------------------------------------------------------------------------
extern "C" void kernel_launch(void* const* d_in, const int* in_sizes, int n_in,
                              void* d_out, int out_size) {
    const int*    neigh_cols   = (const int*)d_in[0];
    const int*    unique_ids   = (const int*)d_in[1];
    const float4* embed_table4 = (const float4*)d_in[2];
    float4*       out4         = (float4*)d_out;

    zero_col_deg_kernel<<<32, 256>>>();
    dedupe_degree_kernel<<<GCN_B / 8, 256>>>(neigh_cols);
    aggregate_kernel<<<GCN_B / AGG_WARPS, 32 * AGG_WARPS>>>(
        neigh_cols, unique_ids, embed_table4, out4);
}

// round 5
// speedup vs baseline: 1.6214x; 1.0468x over previous
#include <cuda_runtime.h>
#include <cuda_bf16.h>
#include <math.h>

// Problem constants (GCNAggregator): B=4096, K=32, U=32768, V=100000, D=128
#define GCN_B 4096
#define GCN_K 32
#define GCN_U 32768
#define GCN_D 128
#define AGG_WARPS 4      // rows (warps) per aggregate block

// Scratch (no cudaMalloc allowed)
__device__ int      g_col_deg[GCN_U];
__device__ unsigned g_row_mask[GCN_B];  // bit k set = k-th entry is first occurrence in its row

// ---------------------------------------------------------------------------
// Kernel 1: per-row dedupe (one warp per row) + column degree accumulation
// ---------------------------------------------------------------------------
__global__ void dedupe_degree_kernel(const int* __restrict__ neigh_cols) {
    int warp_in_block = threadIdx.x >> 5;
    int lane = threadIdx.x & 31;
    int b = blockIdx.x * (blockDim.x >> 5) + warp_in_block;

    int c = neigh_cols[b * GCN_K + lane];

    // first occurrence: no lane j < lane holds the same column
    bool first = true;
    #pragma unroll
    for (int j = 0; j < GCN_K; j++) {
        int cj = __shfl_sync(0xFFFFFFFFu, c, j);
        if (j < lane && cj == c) first = false;
    }

    unsigned mask = __ballot_sync(0xFFFFFFFFu, first);
    if (lane == 0) g_row_mask[b] = mask;
    if (first) atomicAdd(&g_col_deg[c], 1);   // spread addresses -> cheap
}

// ---------------------------------------------------------------------------
// Kernel 2: aggregation. One WARP per row, lane owns 4 consecutive dims.
// Full-burst gather: all 32 LDG.128 issued before any FMA (MLP=32 per thread).
// (off4, w) staged in smem; row scale folded into lane weights; duplicates
// carry w=0 -> branch-free.
// ---------------------------------------------------------------------------
__global__ void __launch_bounds__(32 * AGG_WARPS)
aggregate_kernel(const int* __restrict__ neigh_cols,
                 const int* __restrict__ unique_ids,
                 const float4* __restrict__ embed_table4,  // [V, 32] float4
                 float4* __restrict__ out4) {              // [B, 32] float4
    const int warp = threadIdx.x >> 5;
    const int lane = threadIdx.x & 31;
    const int b = blockIdx.x * AGG_WARPS + warp;

    __shared__ int2 s_wo[AGG_WARPS][GCN_K];   // {row offset in float4 units, bitcast(weight)}

    // ---- prologue: per-lane (offset, weight) -> smem ----
    const unsigned mask = g_row_mask[b];
    {
        int c = neigh_cols[b * GCN_K + lane];
        bool first = (mask >> lane) & 1u;
        float w = 0.0f;
        if (first) {
            int deg = __ldg(&g_col_deg[c]);   // deg >= 1 for first occurrences
            w = rsqrtf((float)deg);
        }
        w *= rsqrtf((float)__popc(mask));     // fold row scale into lane weight
        int off4 = __ldg(&unique_ids[c]) * (GCN_D / 4);
        s_wo[warp][lane] = make_int2(off4, __float_as_int(w));
    }
    __syncwarp();

    // ---- full-burst gather: 32 independent LDG.128 front-batched ----
    float4 buf[GCN_K];
    float  wk[GCN_K];
    #pragma unroll
    for (int k = 0; k < GCN_K; k++) {
        int2 wo = s_wo[warp][k];
        wk[k] = __int_as_float(wo.y);
        buf[k] = __ldg(&embed_table4[wo.x + lane]);
    }

    float4 acc = make_float4(0.f, 0.f, 0.f, 0.f);
    #pragma unroll
    for (int k = 0; k < GCN_K; k++) {
        acc.x = fmaf(wk[k], buf[k].x, acc.x);
        acc.y = fmaf(wk[k], buf[k].y, acc.y);
        acc.z = fmaf(wk[k], buf[k].z, acc.z);
        acc.w = fmaf(wk[k], buf[k].w, acc.w);
    }

    out4[b * (GCN_D / 4) + lane] = acc;
}

// ---------------------------------------------------------------------------
extern "C" void kernel_launch(void* const* d_in, const int* in_sizes, int n_in,
                              void* d_out, int out_size) {
    const int*    neigh_cols   = (const int*)d_in[0];
    const int*    unique_ids   = (const int*)d_in[1];
    const float4* embed_table4 = (const float4*)d_in[2];
    float4*       out4         = (float4*)d_out;

    // Zero column degrees via a graph memset node (no dedicated kernel launch).
    void* col_deg_ptr = nullptr;
    cudaGetSymbolAddress(&col_deg_ptr, g_col_deg);
    cudaMemsetAsync(col_deg_ptr, 0, GCN_U * sizeof(int));

    dedupe_degree_kernel<<<GCN_B / 8, 256>>>(neigh_cols);
    aggregate_kernel<<<GCN_B / AGG_WARPS, 32 * AGG_WARPS>>>(
        neigh_cols, unique_ids, embed_table4, out4);
}